// round 1
// baseline (speedup 1.0000x reference)
#include <cuda_runtime.h>
#include <math.h>

#define CIN   64
#define COUT  128
#define HH    224
#define WW    224
#define OH    222
#define OW    222

#define TB_ROWS 4      // output rows per block
#define TB_COLS 24     // output cols per block
#define PX      12     // pixels per warp (half of TB_COLS)
#define PAT_R   6      // patch rows = TB_ROWS + 2
#define PAT_C   26     // patch cols = TB_COLS + 2
#define PAT_CP  28     // padded patch col stride (16B-aligned rows)

// Transposed weights: [ci][tap][co], tap = kh*3+kw. 64*9*128 floats = 288KB.
__device__ float g_wT[CIN * 9 * COUT];

__global__ void wT_kernel(const float* __restrict__ w) {
    int i = blockIdx.x * 256 + threadIdx.x;
    if (i < CIN * 9 * COUT) {
        int co  = i & 127;
        int t   = i >> 7;       // ci*9 + tap
        int tap = t % 9;
        int ci  = t / 9;
        g_wT[i] = w[co * (CIN * 9) + ci * 9 + tap];
    }
}

__global__ __launch_bounds__(256, 2)
void conv_min_tanh_kernel(const float* __restrict__ x,
                          const float* __restrict__ bias,
                          float* __restrict__ out) {
    __shared__ float spatch[CIN * PAT_R * PAT_CP];   // 43008 B

    const int tid  = threadIdx.x;
    const int b    = blockIdx.z;
    const int row0 = blockIdx.y * TB_ROWS;
    const int col0 = blockIdx.x * TB_COLS;

    // ---- stage input patch (zero-fill out of range) ----
    const float* xb = x + (size_t)b * CIN * HH * WW;
    for (int i = tid; i < CIN * PAT_R * PAT_C; i += 256) {
        int ci  = i / (PAT_R * PAT_C);
        int rem = i - ci * (PAT_R * PAT_C);
        int r   = rem / PAT_C;
        int c   = rem - r * PAT_C;
        int iy = row0 + r, ix = col0 + c;
        float v = 0.0f;
        if (iy < HH && ix < WW) v = xb[(ci * HH + iy) * WW + ix];
        spatch[ci * (PAT_R * PAT_CP) + r * PAT_CP + c] = v;
    }
    __syncthreads();

    const int warp = tid >> 5, lane = tid & 31;
    const int r      = warp >> 1;            // 0..3
    const int colseg = (warp & 1) * PX;      // 0 or 12 (16B-aligned in floats)

    // lane owns co = 4*lane .. 4*lane+3
    float4 bv = *(const float4*)(bias + lane * 4);
    float acc[4][PX];
#pragma unroll
    for (int p = 0; p < PX; p++) {
        acc[0][p] = bv.x; acc[1][p] = bv.y; acc[2][p] = bv.z; acc[3][p] = bv.w;
    }

    const float4* wt4 = (const float4*)g_wT;

    for (int ci = 0; ci < CIN; ci++) {
        const int prow = ci * (PAT_R * PAT_CP) + r * PAT_CP + colseg;
#pragma unroll
        for (int kh = 0; kh < 3; kh++) {
            // lane-uniform broadcast loads of the input row (16 floats >= 12+2+2)
            const float4* xp = (const float4*)(spatch + prow + kh * PAT_CP);
            float xr[16];
#pragma unroll
            for (int j = 0; j < 4; j++) {
                float4 t = xp[j];
                xr[4*j+0] = t.x; xr[4*j+1] = t.y; xr[4*j+2] = t.z; xr[4*j+3] = t.w;
            }
#pragma unroll
            for (int kw = 0; kw < 3; kw++) {
                float4 wv = __ldg(&wt4[(ci * 9 + kh * 3 + kw) * 32 + lane]);
#pragma unroll
                for (int p = 0; p < PX; p++) {
                    float xv = xr[p + kw];
                    acc[0][p] = fmaf(xv, wv.x, acc[0][p]);
                    acc[1][p] = fmaf(xv, wv.y, acc[1][p]);
                    acc[2][p] = fmaf(xv, wv.z, acc[2][p]);
                    acc[3][p] = fmaf(xv, wv.w, acc[3][p]);
                }
            }
        }
    }

    // ---- min over 4 local co, then min across 32 lanes (=> all 128 co) ----
    float keep = 0.0f;
#pragma unroll
    for (int p = 0; p < PX; p++) {
        float m = fminf(fminf(acc[0][p], acc[1][p]), fminf(acc[2][p], acc[3][p]));
#pragma unroll
        for (int off = 16; off; off >>= 1)
            m = fminf(m, __shfl_xor_sync(0xffffffffu, m, off));
        if (lane == p) keep = m;
    }

    const int orow = row0 + r;
    const int ocol = col0 + colseg + lane;
    if (lane < PX && orow < OH && ocol < OW) {
        float v = tanhf(tanhf(keep));
        out[((size_t)b * OH + orow) * OW + ocol] = v;
    }
}

extern "C" void kernel_launch(void* const* d_in, const int* in_sizes, int n_in,
                              void* d_out, int out_size) {
    const float* x    = (const float*)d_in[0];
    const float* w    = (const float*)d_in[1];
    const float* bias = (const float*)d_in[2];
    float* out = (float*)d_out;

    wT_kernel<<<(CIN * 9 * COUT + 255) / 256, 256>>>(w);

    dim3 grid((OW + TB_COLS - 1) / TB_COLS,   // 10
              (OH + TB_ROWS - 1) / TB_ROWS,   // 56
              16);
    conv_min_tanh_kernel<<<grid, dim3(256)>>>(x, bias, out);
}

// round 3
// speedup vs baseline: 1.8162x; 1.8162x over previous
#include <cuda_runtime.h>
#include <cuda_bf16.h>
#include <cstdint>
#include <math.h>

#define CIN   64
#define COUT  128
#define HH    224
#define WW    224
#define OH    222
#define OW    222
#define TILE_PX 126        // valid outputs per x-tile (N=128 computed, 2 halo)
#define SLAB_ROWS 132      // input px rows staged (covers n up to 129)

// ---------------- weight prep ----------------
// g_Wfrag: a-fragment-shuffled weights, [pl(2)][tap(9)][ks(4)][mblk(8)][lane(32)] x uint4
// word0: A[r   ][k..k+1]  word1: A[r+8 ][k..k+1]
// word2: A[r   ][k+8..]   word3: A[r+8 ][k+8..]
// where r = mblk*16 + lane>>2 (co), k = ks*16 + (lane&3)*2 (ci)
__device__ uint4 g_Wfrag[2 * 9 * 4 * 8 * 32];

__global__ void prep_kernel(const float* __restrict__ w) {
    int i = blockIdx.x * 256 + threadIdx.x;
    if (i >= 18432) return;
    int lane = i & 31;
    int mblk = (i >> 5) & 7;
    int q    = i >> 8;            // pl*36 + tap*4 + ks
    int ks   = q & 3;
    int t2   = q >> 2;
    int tap  = t2 % 9;
    int pl   = t2 / 9;
    int kh = tap / 3, kw = tap - kh * 3;

    int r  = lane >> 2;
    int k0 = ks * 16 + (lane & 3) * 2;

    uint32_t words[4];
#pragma unroll
    for (int wi = 0; wi < 4; wi++) {
        int co = mblk * 16 + r + (wi & 1) * 8;
        int kk = k0 + (wi >> 1) * 8;
        uint32_t packed = 0;
#pragma unroll
        for (int j = 0; j < 2; j++) {
            int ci = kk + j;
            float v = w[((co * CIN + ci) * 3 + kh) * 3 + kw];
            __nv_bfloat16 h = __float2bfloat16(v);
            __nv_bfloat16 e = (pl == 0) ? h : __float2bfloat16(v - __bfloat162float(h));
            packed |= (uint32_t)__bfloat16_as_ushort(e) << (16 * j);
        }
        words[wi] = packed;
    }
    g_Wfrag[i] = make_uint4(words[0], words[1], words[2], words[3]);
}

// ---------------- helpers ----------------
__device__ __forceinline__ uint32_t smem_u32(const void* p) {
    uint32_t a;
    asm("{ .reg .u64 t; cvta.to.shared.u64 t, %1; cvt.u32.u64 %0, t; }" : "=r"(a) : "l"(p));
    return a;
}
__device__ __forceinline__ uint32_t swz(uint32_t off) { return off ^ ((off >> 3) & 0x70); }

__device__ __forceinline__ void sts128(uint32_t addr, uint32_t r0, uint32_t r1, uint32_t r2, uint32_t r3) {
    asm volatile("st.shared.v4.b32 [%0], {%1, %2, %3, %4};" :: "r"(addr), "r"(r0), "r"(r1), "r"(r2), "r"(r3) : "memory");
}
__device__ __forceinline__ void ldsm4(uint32_t& r0, uint32_t& r1, uint32_t& r2, uint32_t& r3, uint32_t addr) {
    asm volatile("ldmatrix.sync.aligned.m8n8.x4.shared.b16 {%0, %1, %2, %3}, [%4];"
        : "=r"(r0), "=r"(r1), "=r"(r2), "=r"(r3) : "r"(addr));
}
__device__ __forceinline__ void mma16816(float* d, const uint4& a, uint32_t b0, uint32_t b1) {
    asm volatile("mma.sync.aligned.m16n8k16.row.col.f32.bf16.bf16.f32 "
        "{%0, %1, %2, %3}, {%4, %5, %6, %7}, {%8, %9}, {%0, %1, %2, %3};"
        : "+f"(d[0]), "+f"(d[1]), "+f"(d[2]), "+f"(d[3])
        : "r"(a.x), "r"(a.y), "r"(a.z), "r"(a.w), "r"(b0), "r"(b1));
}

// SMEM: X slabs [kh(3)][pl(2)] of SLAB_ROWS x 128B; epilogue min buffer overlays.
#define SLAB_BYTES (SLAB_ROWS * 128)              // 16896
#define OFF_X(kh, pl) (((kh) * 2 + (pl)) * SLAB_BYTES)
#define SMEM_BYTES (6 * SLAB_BYTES + 1024)        // 102400

__global__ __launch_bounds__(256, 1)
void conv_mma_kernel(const float* __restrict__ x,
                     const float* __restrict__ bias,
                     float* __restrict__ out) {
    extern __shared__ char smem_raw[];
    uint32_t sb = (smem_u32(smem_raw) + 1023u) & ~1023u;

    const int tid  = threadIdx.x;
    const int wid  = tid >> 5;
    const int lane = tid & 31;
    const int b    = blockIdx.z;
    const int oy   = blockIdx.y;
    const int x0   = blockIdx.x * TILE_PX;

    const int warpM = wid & 1;       // M half: co 64*warpM .. +63
    const int warpN = wid >> 1;      // N quarter: px 32*warpN .. +31

    // ---- stage input slabs: [kh][pl][px row][64 ci bf16], SW128 swizzle ----
    const float* xb = x + (size_t)b * CIN * HH * WW;
    for (int kh = 0; kh < 3; kh++) {
        const int y = oy + kh;                     // < 224 always
        for (int t = tid; t < SLAB_ROWS * 8; t += 256) {
            int p   = t % SLAB_ROWS;
            int cig = t / SLAB_ROWS;               // 8-ci group
            int ix  = x0 + p;
            bool ok = (ix < WW);
            float v[8];
#pragma unroll
            for (int j = 0; j < 8; j++)
                v[j] = ok ? __ldg(&xb[((size_t)(cig * 8 + j) * HH + y) * WW + ix]) : 0.0f;
            uint32_t hw[4], lw[4];
#pragma unroll
            for (int k = 0; k < 4; k++) {
                __nv_bfloat16 h0 = __float2bfloat16(v[2*k]);
                __nv_bfloat16 h1 = __float2bfloat16(v[2*k+1]);
                __nv_bfloat16 l0 = __float2bfloat16(v[2*k]   - __bfloat162float(h0));
                __nv_bfloat16 l1 = __float2bfloat16(v[2*k+1] - __bfloat162float(h1));
                hw[k] = (uint32_t)__bfloat16_as_ushort(h0) | ((uint32_t)__bfloat16_as_ushort(h1) << 16);
                lw[k] = (uint32_t)__bfloat16_as_ushort(l0) | ((uint32_t)__bfloat16_as_ushort(l1) << 16);
            }
            uint32_t so = swz((uint32_t)(p * 128 + cig * 16));
            sts128(sb + OFF_X(kh, 0) + so, hw[0], hw[1], hw[2], hw[3]);
            sts128(sb + OFF_X(kh, 1) + so, lw[0], lw[1], lw[2], lw[3]);
        }
    }
    __syncthreads();

    // ---- accumulators, init = bias[co] (bias must precede channel-min) ----
    float acc[4][4][4];
#pragma unroll
    for (int m = 0; m < 4; m++) {
        int r_co = warpM * 64 + m * 16 + (lane >> 2);
        float b0 = __ldg(&bias[r_co]);
        float b1 = __ldg(&bias[r_co + 8]);
#pragma unroll
        for (int f = 0; f < 4; f++) {
            acc[m][f][0] = b0; acc[m][f][1] = b0;
            acc[m][f][2] = b1; acc[m][f][3] = b1;
        }
    }

    const uint4* gw = g_Wfrag;
    const int rowb    = warpN * 32 + (lane & 7) + ((lane >> 4) << 3);
    const int kb_lane = ((lane >> 3) & 1) * 16;
    const int awoff   = warpM * 4;

    for (int tap = 0; tap < 9; tap++) {
        const int kh = tap / 3, kw = tap - kh * 3;
        const uint32_t slabHi = sb + OFF_X(kh, 0);
        const uint32_t slabLo = sb + OFF_X(kh, 1);

#pragma unroll
        for (int ks = 0; ks < 4; ks++) {
            // A fragments: hi & lo planes, 4 m16 blocks each
            uint4 AH[4], AL[4];
            const int baseH = (tap * 4 + ks) * 8;
            const int baseL = (36 + tap * 4 + ks) * 8;
#pragma unroll
            for (int m = 0; m < 4; m++) {
                AH[m] = __ldg(&gw[(baseH + awoff + m) * 32 + lane]);
                AL[m] = __ldg(&gw[(baseL + awoff + m) * 32 + lane]);
            }
            // B fragments via ldmatrix.x4: halves cover n +0..15 / +16..31
            uint32_t BH[8], BL[8];
#pragma unroll
            for (int half = 0; half < 2; half++) {
                uint32_t off = swz((uint32_t)((rowb + half * 16 + kw) * 128 + kb_lane + ks * 32));
                ldsm4(BH[half*4+0], BH[half*4+1], BH[half*4+2], BH[half*4+3], slabHi + off);
                ldsm4(BL[half*4+0], BL[half*4+1], BL[half*4+2], BL[half*4+3], slabLo + off);
            }
            // 3 combos: hi*hi, hi*lo, lo*hi
#pragma unroll
            for (int m = 0; m < 4; m++) {
#pragma unroll
                for (int f = 0; f < 4; f++) {
                    mma16816(acc[m][f], AH[m], BH[f*2], BH[f*2+1]);
                    mma16816(acc[m][f], AH[m], BL[f*2], BL[f*2+1]);
                    mma16816(acc[m][f], AL[m], BH[f*2], BH[f*2+1]);
                }
            }
        }
    }

    // ---- epilogue: min over co ----
    __syncthreads();   // done reading slabs; reuse smem as min buffer
    float* sMin = (float*)(smem_raw + (sb - smem_u32(smem_raw)));  // [2][128]

#pragma unroll
    for (int f = 0; f < 4; f++) {
        float v0 = __int_as_float(0x7f800000), v1 = v0;
#pragma unroll
        for (int m = 0; m < 4; m++) {
            v0 = fminf(v0, fminf(acc[m][f][0], acc[m][f][2]));
            v1 = fminf(v1, fminf(acc[m][f][1], acc[m][f][3]));
        }
        // reduce across lanes sharing the same column (lane>>2 varies)
#pragma unroll
        for (int off = 4; off < 32; off <<= 1) {
            v0 = fminf(v0, __shfl_xor_sync(0xffffffffu, v0, off));
            v1 = fminf(v1, __shfl_xor_sync(0xffffffffu, v1, off));
        }
        if ((lane >> 2) == 0) {
            int px = warpN * 32 + (f >> 1) * 16 + (f & 1) * 8 + (lane & 3) * 2;
            sMin[warpM * 128 + px]     = v0;
            sMin[warpM * 128 + px + 1] = v1;
        }
    }
    __syncthreads();

    if (tid < 128) {
        int p = tid;
        if (p < TILE_PX && x0 + p < OW) {
            float m = fminf(sMin[p], sMin[128 + p]);
            out[((size_t)b * OH + oy) * OW + x0 + p] = tanhf(tanhf(m));
        }
    }
}

extern "C" void kernel_launch(void* const* d_in, const int* in_sizes, int n_in,
                              void* d_out, int out_size) {
    const float* x    = (const float*)d_in[0];
    const float* w    = (const float*)d_in[1];
    const float* bias = (const float*)d_in[2];
    float* out = (float*)d_out;

    prep_kernel<<<(18432 + 255) / 256, 256>>>(w);

    cudaFuncSetAttribute(conv_mma_kernel, cudaFuncAttributeMaxDynamicSharedMemorySize, SMEM_BYTES);
    dim3 grid((OW + TILE_PX - 1) / TILE_PX, OH, 16);   // 2 x 222 x 16
    conv_mma_kernel<<<grid, 256, SMEM_BYTES>>>(x, bias, out);
}

// round 4
// speedup vs baseline: 5.7426x; 3.1619x over previous
#include <cuda_runtime.h>
#include <cuda_fp16.h>
#include <cstdint>
#include <math.h>

#define CIN   64
#define COUT  128
#define HH    224
#define WW    224
#define OH    222
#define OW    222
#define TILE_PX 126        // valid outputs per x-tile (N=128 computed, 2 halo)
#define SLAB_ROWS 132      // input px rows staged (covers n up to 129)

// ---------------- weight prep ----------------
// g_Wfrag: a-fragment-shuffled fp16 weights, [tap(9)][ks(4)][mblk(8)][lane(32)] x uint4
// word0: A[r][k..k+1]  word1: A[r+8][k..k+1]  word2: A[r][k+8..+9]  word3: A[r+8][k+8..+9]
// r = mblk*16 + lane>>2 (co), k = ks*16 + (lane&3)*2 (ci)
__device__ uint4 g_Wfrag[9 * 4 * 8 * 32];

__global__ void prep_kernel(const float* __restrict__ w) {
    int i = blockIdx.x * 256 + threadIdx.x;
    if (i >= 9216) return;
    int lane = i & 31;
    int mblk = (i >> 5) & 7;
    int q    = i >> 8;            // tap*4 + ks
    int ks   = q & 3;
    int tap  = q >> 2;
    int kh = tap / 3, kw = tap - kh * 3;

    int r  = lane >> 2;
    int k0 = ks * 16 + (lane & 3) * 2;

    uint32_t words[4];
#pragma unroll
    for (int wi = 0; wi < 4; wi++) {
        int co = mblk * 16 + r + (wi & 1) * 8;
        int kk = k0 + (wi >> 1) * 8;
        uint32_t packed = 0;
#pragma unroll
        for (int j = 0; j < 2; j++) {
            float v = w[((co * CIN + (kk + j)) * 3 + kh) * 3 + kw];
            __half h = __float2half(v);
            packed |= (uint32_t)__half_as_ushort(h) << (16 * j);
        }
        words[wi] = packed;
    }
    g_Wfrag[i] = make_uint4(words[0], words[1], words[2], words[3]);
}

// ---------------- helpers ----------------
__device__ __forceinline__ uint32_t smem_u32(const void* p) {
    uint32_t a;
    asm("{ .reg .u64 t; cvta.to.shared.u64 t, %1; cvt.u32.u64 %0, t; }" : "=r"(a) : "l"(p));
    return a;
}
__device__ __forceinline__ uint32_t swz(uint32_t off) { return off ^ ((off >> 3) & 0x70); }

__device__ __forceinline__ void sts128(uint32_t addr, uint32_t r0, uint32_t r1, uint32_t r2, uint32_t r3) {
    asm volatile("st.shared.v4.b32 [%0], {%1, %2, %3, %4};" :: "r"(addr), "r"(r0), "r"(r1), "r"(r2), "r"(r3) : "memory");
}
__device__ __forceinline__ void ldsm4(uint32_t& r0, uint32_t& r1, uint32_t& r2, uint32_t& r3, uint32_t addr) {
    asm volatile("ldmatrix.sync.aligned.m8n8.x4.shared.b16 {%0, %1, %2, %3}, [%4];"
        : "=r"(r0), "=r"(r1), "=r"(r2), "=r"(r3) : "r"(addr));
}
__device__ __forceinline__ void mma16816(float* d, const uint4& a, uint32_t b0, uint32_t b1) {
    asm volatile("mma.sync.aligned.m16n8k16.row.col.f32.f16.f16.f32 "
        "{%0, %1, %2, %3}, {%4, %5, %6, %7}, {%8, %9}, {%0, %1, %2, %3};"
        : "+f"(d[0]), "+f"(d[1]), "+f"(d[2]), "+f"(d[3])
        : "r"(a.x), "r"(a.y), "r"(a.z), "r"(a.w), "r"(b0), "r"(b1));
}

// SMEM: 3 X slabs of SLAB_ROWS x 128B (fp16, [px row][64 ci]); min buffer overlays.
#define SLAB_BYTES (SLAB_ROWS * 128)              // 16896
#define OFF_X(kh) ((kh) * SLAB_BYTES)
#define SMEM_BYTES (3 * SLAB_BYTES + 1024)        // 51712

__global__ __launch_bounds__(256, 2)
void conv_mma_kernel(const float* __restrict__ x,
                     const float* __restrict__ bias,
                     float* __restrict__ out) {
    extern __shared__ char smem_raw[];
    uint32_t sb = (smem_u32(smem_raw) + 1023u) & ~1023u;

    const int tid  = threadIdx.x;
    const int wid  = tid >> 5;
    const int lane = tid & 31;
    const int b    = blockIdx.z;
    const int oy   = blockIdx.y;
    const int x0   = blockIdx.x * TILE_PX;

    const int warpM = wid & 1;       // M half: co 64*warpM .. +63
    const int warpN = wid >> 1;      // N quarter: px 32*warpN .. +31

    // ---- stage input slabs: [kh][px row][64 ci fp16], SW128 swizzle ----
    const float* xb = x + (size_t)b * CIN * HH * WW;
    for (int kh = 0; kh < 3; kh++) {
        const int y = oy + kh;                     // < 224 always
        for (int t = tid; t < SLAB_ROWS * 8; t += 256) {
            int p   = t % SLAB_ROWS;
            int cig = t / SLAB_ROWS;               // 8-ci group
            int ix  = x0 + p;
            bool ok = (ix < WW);
            float v[8];
#pragma unroll
            for (int j = 0; j < 8; j++)
                v[j] = ok ? __ldg(&xb[((size_t)(cig * 8 + j) * HH + y) * WW + ix]) : 0.0f;
            uint32_t hw[4];
#pragma unroll
            for (int k = 0; k < 4; k++) {
                __half2 h2 = __floats2half2_rn(v[2*k], v[2*k+1]);
                hw[k] = *(uint32_t*)&h2;
            }
            uint32_t so = swz((uint32_t)(p * 128 + cig * 16));
            sts128(sb + OFF_X(kh) + so, hw[0], hw[1], hw[2], hw[3]);
        }
    }
    __syncthreads();

    // ---- accumulators, init = bias[co] (bias must precede channel-min) ----
    float acc[4][4][4];
#pragma unroll
    for (int m = 0; m < 4; m++) {
        int r_co = warpM * 64 + m * 16 + (lane >> 2);
        float b0 = __ldg(&bias[r_co]);
        float b1 = __ldg(&bias[r_co + 8]);
#pragma unroll
        for (int f = 0; f < 4; f++) {
            acc[m][f][0] = b0; acc[m][f][1] = b0;
            acc[m][f][2] = b1; acc[m][f][3] = b1;
        }
    }

    const uint4* gw = g_Wfrag;
    const int rowb    = warpN * 32 + (lane & 7) + ((lane >> 4) << 3);
    const int kb_lane = ((lane >> 3) & 1) * 16;
    const int awoff   = warpM * 4;

    for (int tap = 0; tap < 9; tap++) {
        const int kh = tap / 3, kw = tap - kh * 3;
        const uint32_t slab = sb + OFF_X(kh);

#pragma unroll
        for (int ks = 0; ks < 4; ks++) {
            uint4 A[4];
            const int base = (tap * 4 + ks) * 8;
#pragma unroll
            for (int m = 0; m < 4; m++)
                A[m] = __ldg(&gw[(base + awoff + m) * 32 + lane]);

            uint32_t B[8];
#pragma unroll
            for (int half = 0; half < 2; half++) {
                uint32_t off = swz((uint32_t)((rowb + half * 16 + kw) * 128 + kb_lane + ks * 32));
                ldsm4(B[half*4+0], B[half*4+1], B[half*4+2], B[half*4+3], slab + off);
            }
#pragma unroll
            for (int m = 0; m < 4; m++) {
#pragma unroll
                for (int f = 0; f < 4; f++)
                    mma16816(acc[m][f], A[m], B[f*2], B[f*2+1]);
            }
        }
    }

    // ---- epilogue: min over co ----
    __syncthreads();   // done reading slabs; reuse smem as min buffer
    float* sMin = (float*)(smem_raw + (sb - smem_u32(smem_raw)));  // [2][128]

#pragma unroll
    for (int f = 0; f < 4; f++) {
        float v0 = __int_as_float(0x7f800000), v1 = v0;
#pragma unroll
        for (int m = 0; m < 4; m++) {
            v0 = fminf(v0, fminf(acc[m][f][0], acc[m][f][2]));
            v1 = fminf(v1, fminf(acc[m][f][1], acc[m][f][3]));
        }
#pragma unroll
        for (int off = 4; off < 32; off <<= 1) {
            v0 = fminf(v0, __shfl_xor_sync(0xffffffffu, v0, off));
            v1 = fminf(v1, __shfl_xor_sync(0xffffffffu, v1, off));
        }
        if ((lane >> 2) == 0) {
            int px = warpN * 32 + (f >> 1) * 16 + (f & 1) * 8 + (lane & 3) * 2;
            sMin[warpM * 128 + px]     = v0;
            sMin[warpM * 128 + px + 1] = v1;
        }
    }
    __syncthreads();

    if (tid < 128) {
        int p = tid;
        if (p < TILE_PX && x0 + p < OW) {
            float m = fminf(sMin[p], sMin[128 + p]);
            out[((size_t)b * OH + oy) * OW + x0 + p] = tanhf(tanhf(m));
        }
    }
}

extern "C" void kernel_launch(void* const* d_in, const int* in_sizes, int n_in,
                              void* d_out, int out_size) {
    const float* x    = (const float*)d_in[0];
    const float* w    = (const float*)d_in[1];
    const float* bias = (const float*)d_in[2];
    float* out = (float*)d_out;

    prep_kernel<<<(9216 + 255) / 256, 256>>>(w);

    cudaFuncSetAttribute(conv_mma_kernel, cudaFuncAttributeMaxDynamicSharedMemorySize, SMEM_BYTES);
    dim3 grid((OW + TILE_PX - 1) / TILE_PX, OH, 16);   // 2 x 222 x 16
    conv_mma_kernel<<<grid, 256, SMEM_BYTES>>>(x, bias, out);
}

// round 5
// speedup vs baseline: 7.1799x; 1.2503x over previous
#include <cuda_runtime.h>
#include <cuda_fp16.h>
#include <cstdint>
#include <math.h>

#define CIN   64
#define COUT  128
#define HH    224
#define WW    224
#define OH    222
#define OW    222

#define TPX    32          // output px per tile (x)
#define TROWS  4           // output rows per tile (y)
#define INROWS 6           // staged input rows = TROWS + 2
#define PXST   34          // staged px per row = TPX + 2
#define PXPAD  40          // padded row count (stride), 40*128B = 5120B
#define SLAB_STRIDE 5120   // bytes per input row slab (multiple of 1024)

// ---------------- weight prep ----------------
// g_Wfrag: a-fragment-shuffled fp16 weights, [tap(9)][ks(4)][mblk(8)][lane(32)] x uint4
__device__ uint4 g_Wfrag[9 * 4 * 8 * 32];

__global__ void prep_kernel(const float* __restrict__ w) {
    int i = blockIdx.x * 256 + threadIdx.x;
    if (i >= 9216) return;
    int lane = i & 31;
    int mblk = (i >> 5) & 7;
    int q    = i >> 8;            // tap*4 + ks
    int ks   = q & 3;
    int tap  = q >> 2;
    int kh = tap / 3, kw = tap - kh * 3;

    int r  = lane >> 2;
    int k0 = ks * 16 + (lane & 3) * 2;

    uint32_t words[4];
#pragma unroll
    for (int wi = 0; wi < 4; wi++) {
        int co = mblk * 16 + r + (wi & 1) * 8;
        int kk = k0 + (wi >> 1) * 8;
        uint32_t packed = 0;
#pragma unroll
        for (int j = 0; j < 2; j++) {
            float v = w[((co * CIN + (kk + j)) * 3 + kh) * 3 + kw];
            packed |= (uint32_t)__half_as_ushort(__float2half(v)) << (16 * j);
        }
        words[wi] = packed;
    }
    g_Wfrag[i] = make_uint4(words[0], words[1], words[2], words[3]);
}

// ---------------- helpers ----------------
__device__ __forceinline__ uint32_t smem_u32(const void* p) {
    uint32_t a;
    asm("{ .reg .u64 t; cvta.to.shared.u64 t, %1; cvt.u32.u64 %0, t; }" : "=r"(a) : "l"(p));
    return a;
}
__device__ __forceinline__ uint32_t swz(uint32_t off) { return off ^ ((off >> 3) & 0x70); }

__device__ __forceinline__ void sts128(uint32_t addr, uint32_t r0, uint32_t r1, uint32_t r2, uint32_t r3) {
    asm volatile("st.shared.v4.b32 [%0], {%1, %2, %3, %4};" :: "r"(addr), "r"(r0), "r"(r1), "r"(r2), "r"(r3) : "memory");
}
__device__ __forceinline__ void ldsm4(uint32_t& r0, uint32_t& r1, uint32_t& r2, uint32_t& r3, uint32_t addr) {
    asm volatile("ldmatrix.sync.aligned.m8n8.x4.shared.b16 {%0, %1, %2, %3}, [%4];"
        : "=r"(r0), "=r"(r1), "=r"(r2), "=r"(r3) : "r"(addr));
}
__device__ __forceinline__ void mma16816(float* d, const uint4& a, uint32_t b0, uint32_t b1) {
    asm volatile("mma.sync.aligned.m16n8k16.row.col.f32.f16.f16.f32 "
        "{%0, %1, %2, %3}, {%4, %5, %6, %7}, {%8, %9}, {%0, %1, %2, %3};"
        : "+f"(d[0]), "+f"(d[1]), "+f"(d[2]), "+f"(d[3])
        : "r"(a.x), "r"(a.y), "r"(a.z), "r"(a.w), "r"(b0), "r"(b1));
}

#define SMEM_BYTES (INROWS * SLAB_STRIDE + 1024)   // 31744

__global__ __launch_bounds__(256, 2)
void conv_mma_kernel(const float* __restrict__ x,
                     const float* __restrict__ bias,
                     float* __restrict__ out) {
    extern __shared__ char smem_raw[];
    uint32_t sb = (smem_u32(smem_raw) + 1023u) & ~1023u;

    const int tid  = threadIdx.x;
    const int wid  = tid >> 5;
    const int lane = tid & 31;
    const int b    = blockIdx.z;
    const int oy0  = blockIdx.y * TROWS;
    const int x0   = blockIdx.x * TPX;

    const int warpM = wid & 1;       // co half: 64*warpM .. +63
    const int warpN = wid >> 1;      // output row within tile: 0..3

    // ---- stage input: [irow(6)][px(34, pad 40)][64 ci fp16], SW128 swizzle ----
    const float* xb = x + (size_t)b * CIN * HH * WW;
    for (int t = tid; t < INROWS * PXST * 8; t += 256) {   // 1632
        int px   = t % PXST;
        int rc   = t / PXST;
        int cig  = rc & 7;          // 8-ci group
        int irow = rc >> 3;         // 0..5
        int y  = oy0 + irow;
        int ix = x0 + px;
        bool ok = (y < HH) && (ix < WW);
        float v[8];
#pragma unroll
        for (int j = 0; j < 8; j++)
            v[j] = ok ? __ldg(&xb[((size_t)(cig * 8 + j) * HH + y) * WW + ix]) : 0.0f;
        uint32_t hw[4];
#pragma unroll
        for (int k = 0; k < 4; k++) {
            __half2 h2 = __floats2half2_rn(v[2*k], v[2*k+1]);
            hw[k] = *(uint32_t*)&h2;
        }
        uint32_t so = (uint32_t)(irow * SLAB_STRIDE) + swz((uint32_t)(px * 128 + cig * 16));
        sts128(sb + so, hw[0], hw[1], hw[2], hw[3]);
    }
    __syncthreads();

    // ---- accumulators, init = bias[co] ----
    float acc[4][4][4];
#pragma unroll
    for (int m = 0; m < 4; m++) {
        int r_co = warpM * 64 + m * 16 + (lane >> 2);
        float b0 = __ldg(&bias[r_co]);
        float b1 = __ldg(&bias[r_co + 8]);
#pragma unroll
        for (int f = 0; f < 4; f++) {
            acc[m][f][0] = b0; acc[m][f][1] = b0;
            acc[m][f][2] = b1; acc[m][f][3] = b1;
        }
    }

    const uint4* gw = g_Wfrag;
    const int rowpx   = (lane & 7) + ((lane >> 4) << 3);   // 0..15
    const int kb_lane = ((lane >> 3) & 1) * 16;
    const int awoff   = warpM * 4;

    for (int tap = 0; tap < 9; tap++) {
        const int kh = tap / 3, kw = tap - kh * 3;
        const uint32_t slab = sb + (uint32_t)((warpN + kh) * SLAB_STRIDE);

#pragma unroll
        for (int ks = 0; ks < 4; ks++) {
            uint4 A[4];
            const int base = (tap * 4 + ks) * 8;
#pragma unroll
            for (int m = 0; m < 4; m++)
                A[m] = __ldg(&gw[(base + awoff + m) * 32 + lane]);

            uint32_t B[8];
#pragma unroll
            for (int half = 0; half < 2; half++) {
                uint32_t off = swz((uint32_t)((rowpx + half * 16 + kw) * 128 + kb_lane + ks * 32));
                ldsm4(B[half*4+0], B[half*4+1], B[half*4+2], B[half*4+3], slab + off);
            }
#pragma unroll
            for (int m = 0; m < 4; m++) {
#pragma unroll
                for (int f = 0; f < 4; f++)
                    mma16816(acc[m][f], A[m], B[f*2], B[f*2+1]);
            }
        }
    }

    // ---- epilogue: min over co ----
    __syncthreads();   // all warps done reading slabs; reuse smem
    float* sMin = (float*)(smem_raw + (sb - smem_u32(smem_raw)));  // [2][128]

#pragma unroll
    for (int f = 0; f < 4; f++) {
        float v0 = __int_as_float(0x7f800000), v1 = v0;
#pragma unroll
        for (int m = 0; m < 4; m++) {
            v0 = fminf(v0, fminf(acc[m][f][0], acc[m][f][2]));
            v1 = fminf(v1, fminf(acc[m][f][1], acc[m][f][3]));
        }
#pragma unroll
        for (int off = 4; off < 32; off <<= 1) {
            v0 = fminf(v0, __shfl_xor_sync(0xffffffffu, v0, off));
            v1 = fminf(v1, __shfl_xor_sync(0xffffffffu, v1, off));
        }
        if ((lane >> 2) == 0) {
            int px = (f >> 1) * 16 + (f & 1) * 8 + (lane & 3) * 2;  // 0..31 within row
            int idx = warpN * TPX + px;
            sMin[warpM * 128 + idx]     = v0;
            sMin[warpM * 128 + idx + 1] = v1;
        }
    }
    __syncthreads();

    if (tid < 128) {
        int r = tid >> 5, c = tid & 31;
        int orow = oy0 + r, ocol = x0 + c;
        if (orow < OH && ocol < OW) {
            float m = fminf(sMin[tid], sMin[128 + tid]);
            out[((size_t)b * OH + orow) * OW + ocol] = tanhf(tanhf(m));
        }
    }
}

extern "C" void kernel_launch(void* const* d_in, const int* in_sizes, int n_in,
                              void* d_out, int out_size) {
    const float* x    = (const float*)d_in[0];
    const float* w    = (const float*)d_in[1];
    const float* bias = (const float*)d_in[2];
    float* out = (float*)d_out;

    prep_kernel<<<(9216 + 255) / 256, 256>>>(w);

    cudaFuncSetAttribute(conv_mma_kernel, cudaFuncAttributeMaxDynamicSharedMemorySize, SMEM_BYTES);
    dim3 grid((OW + TPX - 1) / TPX,      // 7
              (OH + TROWS - 1) / TROWS,  // 56
              16);
    conv_mma_kernel<<<grid, 256, SMEM_BYTES>>>(x, bias, out);
}

// round 7
// speedup vs baseline: 7.4446x; 1.0369x over previous
#include <cuda_runtime.h>
#include <cuda_fp16.h>
#include <cstdint>
#include <math.h>

#define CIN   64
#define COUT  128
#define HH    224
#define WW    224
#define OH    222
#define OW    222

#define TPX    32          // output px per tile (x)
#define TROWS  4           // output rows per tile (y)
#define INROWS 6           // staged input rows = TROWS + 2
#define PXST   34          // staged px per row = TPX + 2
#define SLAB_STRIDE 5120   // bytes per input row slab (multiple of 1024)

// ---------------- global scratch ----------------
// fp16 transposed input: [b][y][px][ci], 16*224*224*64 halfs (~103MB)
__device__ __half g_xh[(size_t)16 * HH * WW * CIN];
// a-fragment-shuffled fp16 weights: [tap(9)][ks(4)][mblk(8)][lane(32)] x uint4
__device__ uint4 g_Wfrag[9 * 4 * 8 * 32];

__global__ void prep_w(const float* __restrict__ w) {
    int i = blockIdx.x * 256 + threadIdx.x;
    if (i >= 9216) return;
    int lane = i & 31;
    int mblk = (i >> 5) & 7;
    int q    = i >> 8;            // tap*4 + ks
    int ks   = q & 3;
    int tap  = q >> 2;
    int kh = tap / 3, kw = tap - kh * 3;

    int r  = lane >> 2;
    int k0 = ks * 16 + (lane & 3) * 2;

    uint32_t words[4];
#pragma unroll
    for (int wi = 0; wi < 4; wi++) {
        int co = mblk * 16 + r + (wi & 1) * 8;
        int kk = k0 + (wi >> 1) * 8;
        uint32_t packed = 0;
#pragma unroll
        for (int j = 0; j < 2; j++) {
            float v = w[((co * CIN + (kk + j)) * 3 + kh) * 3 + kw];
            packed |= (uint32_t)__half_as_ushort(__float2half(v)) << (16 * j);
        }
        words[wi] = packed;
    }
    g_Wfrag[i] = make_uint4(words[0], words[1], words[2], words[3]);
}

// ---- transpose+convert: x[b][ci][y][px] fp32 -> g_xh[b][y][px][ci] fp16 ----
#define TSTR 72   // smem half-stride per px row (144B, 16B-aligned)
__global__ __launch_bounds__(256)
void prep_x(const float* __restrict__ x) {
    __shared__ __half sT[64 * TSTR];   // [px(64)][ci(64)] halfs
    const int b   = blockIdx.z;
    const int y   = blockIdx.y;
    const int px0 = blockIdx.x * 64;
    const int t   = threadIdx.x;
    const int wid = t >> 5, lane = t & 31;

    const int px = (wid & 1) * 32 + lane;
    const int ip = px0 + px;
    const bool okx = ip < WW;
    const int cib = wid >> 1;          // 0..3
#pragma unroll
    for (int k = 0; k < 16; k++) {
        int ci = cib + k * 4;
        float v = okx ? __ldg(&x[(((size_t)b * CIN + ci) * HH + y) * WW + ip]) : 0.0f;
        sT[px * TSTR + ci] = __float2half(v);
    }
    __syncthreads();

    for (int c = t; c < 512; c += 256) {      // 64 px * 8 cig chunks of 16B
        int pxw = c >> 3, cig = c & 7;
        int ipw = px0 + pxw;
        if (ipw < WW) {
            uint4 val = *(const uint4*)&sT[pxw * TSTR + cig * 8];
            *(uint4*)((char*)g_xh + (((size_t)(b * HH + y) * WW + ipw) << 7) + (cig << 4)) = val;
        }
    }
}

// ---------------- helpers ----------------
__device__ __forceinline__ uint32_t smem_u32(const void* p) {
    uint32_t a;
    asm("{ .reg .u64 t; cvta.to.shared.u64 t, %1; cvt.u32.u64 %0, t; }" : "=r"(a) : "l"(p));
    return a;
}
__device__ __forceinline__ uint32_t swz(uint32_t off) { return off ^ ((off >> 3) & 0x70); }

__device__ __forceinline__ void ldsm4(uint32_t& r0, uint32_t& r1, uint32_t& r2, uint32_t& r3, uint32_t addr) {
    asm volatile("ldmatrix.sync.aligned.m8n8.x4.shared.b16 {%0, %1, %2, %3}, [%4];"
        : "=r"(r0), "=r"(r1), "=r"(r2), "=r"(r3) : "r"(addr));
}
__device__ __forceinline__ void mma16816(float* d, const uint4& a, uint32_t b0, uint32_t b1) {
    asm volatile("mma.sync.aligned.m16n8k16.row.col.f32.f16.f16.f32 "
        "{%0, %1, %2, %3}, {%4, %5, %6, %7}, {%8, %9}, {%0, %1, %2, %3};"
        : "+f"(d[0]), "+f"(d[1]), "+f"(d[2]), "+f"(d[3])
        : "r"(a.x), "r"(a.y), "r"(a.z), "r"(a.w), "r"(b0), "r"(b1));
}
__device__ __forceinline__ void cp16(uint32_t dst, const void* src, int sz) {
    asm volatile("cp.async.cg.shared.global [%0], [%1], 16, %2;"
        :: "r"(dst), "l"(src), "r"(sz) : "memory");
}

#define OFF_MIN (INROWS * SLAB_STRIDE)            // 30720
#define SMEM_BYTES (OFF_MIN + 1024 + 1024)        // slabs + sMin + align slack

__global__ __launch_bounds__(256, 2)
void conv_mma_kernel(const float* __restrict__ bias,
                     float* __restrict__ out) {
    extern __shared__ char smem_raw[];
    uint32_t sb = (smem_u32(smem_raw) + 1023u) & ~1023u;

    const int tid  = threadIdx.x;
    const int wid  = tid >> 5;
    const int lane = tid & 31;
    const int b    = blockIdx.z;
    const int oy0  = blockIdx.y * TROWS;
    const int x0   = blockIdx.x * TPX;

    const int warpM = wid & 1;       // co half: 64*warpM .. +63
    const int warpN = wid >> 1;      // output row within tile: 0..3

    // ---- async-stage slabs: [irow(6)][px(34)][64 ci fp16], SW128 swizzle ----
    // one commit group per input row; chunk = 16B (8 ci)
    for (int g = 0; g < INROWS; g++) {
        int y = oy0 + g;
#pragma unroll 1
        for (int c = tid; c < PXST * 8; c += 256) {   // 272 chunks: tid + maybe tid+256
            int px  = c >> 3;
            int cig = c & 7;
            int ix  = x0 + px;
            bool ok = (y < HH) && (ix < WW);
            const char* src = (const char*)g_xh +
                (ok ? ((((size_t)(b * HH + y) * WW + ix) << 7) + ((size_t)cig << 4)) : 0);
            uint32_t dst = sb + (uint32_t)(g * SLAB_STRIDE)
                         + (uint32_t)(px * 128 + ((cig ^ (px & 7)) << 4));
            cp16(dst, src, ok ? 16 : 0);
        }
        asm volatile("cp.async.commit_group;" ::: "memory");
    }

    // ---- accumulators, init = bias[co] (overlaps with cp.async flight) ----
    float acc[4][4][4];
#pragma unroll
    for (int m = 0; m < 4; m++) {
        int r_co = warpM * 64 + m * 16 + (lane >> 2);
        float b0 = __ldg(&bias[r_co]);
        float b1 = __ldg(&bias[r_co + 8]);
#pragma unroll
        for (int f = 0; f < 4; f++) {
            acc[m][f][0] = b0; acc[m][f][1] = b0;
            acc[m][f][2] = b1; acc[m][f][3] = b1;
        }
    }

    const uint4* gw = g_Wfrag;
    const int rowpx   = (lane & 7) + ((lane >> 4) << 3);   // 0..15
    const int kb_lane = ((lane >> 3) & 1) * 16;
    const int awoff   = warpM * 4;

#pragma unroll
    for (int kh = 0; kh < 3; kh++) {
        if (kh == 0)      asm volatile("cp.async.wait_group 2;" ::: "memory");
        else if (kh == 1) asm volatile("cp.async.wait_group 1;" ::: "memory");
        else              asm volatile("cp.async.wait_group 0;" ::: "memory");
        __syncthreads();

        const uint32_t slab = sb + (uint32_t)((warpN + kh) * SLAB_STRIDE);
#pragma unroll
        for (int kw = 0; kw < 3; kw++) {
            const int tap = kh * 3 + kw;
#pragma unroll
            for (int ks = 0; ks < 4; ks++) {
                uint4 A[4];
                const int base = (tap * 4 + ks) * 8;
#pragma unroll
                for (int m = 0; m < 4; m++)
                    A[m] = __ldg(&gw[(base + awoff + m) * 32 + lane]);

                uint32_t B[8];
#pragma unroll
                for (int half = 0; half < 2; half++) {
                    uint32_t off = swz((uint32_t)((rowpx + half * 16 + kw) * 128 + kb_lane + ks * 32));
                    ldsm4(B[half*4+0], B[half*4+1], B[half*4+2], B[half*4+3], slab + off);
                }
#pragma unroll
                for (int m = 0; m < 4; m++) {
#pragma unroll
                    for (int f = 0; f < 4; f++)
                        mma16816(acc[m][f], A[m], B[f*2], B[f*2+1]);
                }
            }
        }
    }

    // ---- epilogue: min over co ----
    float* sMin = (float*)(smem_raw + (sb - smem_u32(smem_raw)) + OFF_MIN);  // [2][128]

#pragma unroll
    for (int f = 0; f < 4; f++) {
        float v0 = __int_as_float(0x7f800000), v1 = v0;
#pragma unroll
        for (int m = 0; m < 4; m++) {
            v0 = fminf(v0, fminf(acc[m][f][0], acc[m][f][2]));
            v1 = fminf(v1, fminf(acc[m][f][1], acc[m][f][3]));
        }
#pragma unroll
        for (int off = 4; off < 32; off <<= 1) {
            v0 = fminf(v0, __shfl_xor_sync(0xffffffffu, v0, off));
            v1 = fminf(v1, __shfl_xor_sync(0xffffffffu, v1, off));
        }
        if ((lane >> 2) == 0) {
            int px = (f >> 1) * 16 + (f & 1) * 8 + (lane & 3) * 2;  // 0..31 within row
            int idx = warpN * TPX + px;
            sMin[warpM * 128 + idx]     = v0;
            sMin[warpM * 128 + idx + 1] = v1;
        }
    }
    __syncthreads();

    if (tid < 128) {
        int r = tid >> 5, c = tid & 31;
        int orow = oy0 + r, ocol = x0 + c;
        if (orow < OH && ocol < OW) {
            float m = fminf(sMin[tid], sMin[128 + tid]);
            out[((size_t)b * OH + orow) * OW + ocol] = tanhf(tanhf(m));
        }
    }
}

extern "C" void kernel_launch(void* const* d_in, const int* in_sizes, int n_in,
                              void* d_out, int out_size) {
    const float* x    = (const float*)d_in[0];
    const float* w    = (const float*)d_in[1];
    const float* bias = (const float*)d_in[2];
    float* out = (float*)d_out;

    prep_w<<<(9216 + 255) / 256, 256>>>(w);
    prep_x<<<dim3(4, HH, 16), 256>>>(x);

    cudaFuncSetAttribute(conv_mma_kernel, cudaFuncAttributeMaxDynamicSharedMemorySize, SMEM_BYTES);
    dim3 grid((OW + TPX - 1) / TPX,      // 7
              (OH + TROWS - 1) / TROWS,  // 56
              16);
    conv_mma_kernel<<<grid, 256, SMEM_BYTES>>>(bias, out);
}